// round 4
// baseline (speedup 1.0000x reference)
#include <cuda_runtime.h>
#include <cstdint>

// ============================================================================
// CINLayer: out_mat[b,c,d] = sum_{i,j} kernel[c,i,j] * x[b,i,d] * y[b,j,d]
//           final[b,c]     = sum_d out_mat[b,c,d]
// GEMM mapping: Z[(b,d),(i,j)] = x[b,i,d]*y[b,j,d] (built in regs, fp16)
//               out = Z(131072 x 1024) @ kernel^T(1024 x 64)
// via mma.sync.m16n8k16.f32.f16.f16.f32 (baseline PTX, works on sm_103).
// Persistent grid: 148 CTAs x 256 threads, 1024 passes of 128 rows.
// ============================================================================

#define B_DIM 4096
#define H_DIM 32
#define C_DIM 64
#define D_DIM 32

namespace cin {

constexpr int THREADS   = 256;
constexpr int GRID      = 148;
constexpr int PASS_ROWS = 128;                       // 4 b's x 32 d per pass
constexpr int N_PASSES  = (B_DIM * D_DIM) / PASS_ROWS;  // 1024
constexpr int KSTEPS    = 64;                        // K=1024 / k16

// SMEM (bytes)
constexpr int SM_KP  = 0;                 // packed fp16 kernel fragments: 128KB
constexpr int KP_SZ  = KSTEPS * 4 * 32 * 16;            // 131072
constexpr int SM_XS  = SM_KP + KP_SZ;     // x stage: [i][row] 32*128 f32 = 16KB
constexpr int SM_YS  = SM_XS + 32 * 128 * 4;
constexpr int SM_BUF = SM_YS + 32 * 128 * 4;            // epi: [row][73] f32
constexpr int BUF_STRIDE = 73;
constexpr unsigned SMEM_TOTAL = SM_BUF + PASS_ROWS * BUF_STRIDE * 4;  // ~201KB

__device__ __forceinline__ uint32_t smem_u32(const void* p) {
    uint32_t a;
    asm("{ .reg .u64 t; cvta.to.shared.u64 t, %1; cvt.u32.u64 %0, t; }"
        : "=r"(a) : "l"(p));
    return a;
}
// pack two f32 -> f16x2 (lo = second operand)
__device__ __forceinline__ uint32_t cvt2(float hi, float lo) {
    uint32_t r;
    asm("cvt.rn.f16x2.f32 %0, %1, %2;" : "=r"(r) : "f"(hi), "f"(lo));
    return r;
}
__device__ __forceinline__ void sts32(uint32_t a, uint32_t v) {
    asm volatile("st.shared.b32 [%0], %1;" :: "r"(a), "r"(v) : "memory");
}
__device__ __forceinline__ void sts32f(uint32_t a, float v) {
    asm volatile("st.shared.f32 [%0], %1;" :: "r"(a), "f"(v) : "memory");
}
__device__ __forceinline__ void sts128f(uint32_t a, float4 v) {
    asm volatile("st.shared.v4.f32 [%0], {%1,%2,%3,%4};"
                 :: "r"(a), "f"(v.x), "f"(v.y), "f"(v.z), "f"(v.w) : "memory");
}
__device__ __forceinline__ float ldsf(uint32_t a) {
    float v;
    asm volatile("ld.shared.f32 %0, [%1];" : "=f"(v) : "r"(a));
    return v;
}
__device__ __forceinline__ void lds128(uint32_t* r, uint32_t a) {
    asm volatile("ld.shared.v4.b32 {%0,%1,%2,%3}, [%4];"
                 : "=r"(r[0]), "=r"(r[1]), "=r"(r[2]), "=r"(r[3]) : "r"(a));
}
__device__ __forceinline__ void mma16816(float* c, uint32_t a0, uint32_t a1,
                                         uint32_t a2, uint32_t a3,
                                         uint32_t b0, uint32_t b1) {
    asm volatile(
        "mma.sync.aligned.m16n8k16.row.col.f32.f16.f16.f32 "
        "{%0,%1,%2,%3}, {%4,%5,%6,%7}, {%8,%9}, {%0,%1,%2,%3};"
        : "+f"(c[0]), "+f"(c[1]), "+f"(c[2]), "+f"(c[3])
        : "r"(a0), "r"(a1), "r"(a2), "r"(a3), "r"(b0), "r"(b1));
}

__global__ void __launch_bounds__(THREADS)
cin_kernel(const float* __restrict__ X, const float* __restrict__ Y,
           const float* __restrict__ Kmat, float* __restrict__ out_mat,
           float* __restrict__ out_fin) {
    extern __shared__ char smem[];
    const uint32_t sb = smem_u32(smem);
    const int tid  = threadIdx.x;
    const int w    = tid >> 5;
    const int lane = tid & 31;
    const int g    = lane >> 2;     // row group within fragment
    const int t3   = lane & 3;      // col group within fragment
    const int r1   = w * 16 + g;    // pass-local row 1
    const int r2   = r1 + 8;        // pass-local row 2

    // ---------------- stage kernel into fragment-packed fp16 SMEM -----------
    // word layout: addr = ((s*4 + q)*32 + l)*16 + w_in*4
    //   s: k16-step (0..63), q: LDS.128 chunk (0..3), l: lane, w_in: 0..3
    //   chunk q of lane l = frags t=2q (b0,b1), t=2q+1 (b0,b1)
    //   frag t covers n = t*8 + (l>>2); k = (l&3)*2 + {0,1} + 8*hi
    {
        const float4* K4 = reinterpret_cast<const float4*>(Kmat);
        for (int it = 0; it < 64; it++) {
            const int idx  = tid + it * 256;     // float4 index
            const float4 v = K4[idx];
            const int flat = idx * 4;
            const int c    = flat >> 10;
            const int Kk   = flat & 1023;
            const int s    = Kk >> 4;
            const int kk   = Kk & 15;            // multiple of 4
            const int tt   = c >> 3;
            const int q    = tt >> 1;
            const int hi   = kk >> 3;
            const int w_in = (tt & 1) * 2 + hi;
            const int l0   = (c & 7) * 4 + ((kk & 7) >> 1);
            const uint32_t addr =
                sb + SM_KP + (((s * 4 + q) * 32 + l0) << 4) + (w_in << 2);
            sts32(addr,      cvt2(v.y, v.x));
            sts32(addr + 16, cvt2(v.w, v.z));    // next l
        }
    }
    __syncthreads();

    // ---------------- persistent loop over passes ---------------------------
    for (int p = blockIdx.x; p < N_PASSES; p += GRID) {
        // stage x,y for this pass: xs[i][row], ys[j][row], row = b_l*32 + d
        {
            const float4* Xp = reinterpret_cast<const float4*>(X + p * 4096);
            const float4* Yp = reinterpret_cast<const float4*>(Y + p * 4096);
#pragma unroll
            for (int it = 0; it < 4; it++) {
                const int idx = tid + it * 256;        // float4 idx, 0..1023
                const float4 xv = Xp[idx];
                const float4 yv = Yp[idx];
                const int b_l = idx >> 8;
                const int i   = (idx >> 3) & 31;
                const int d4  = (idx & 7) * 4;
                const uint32_t off = (uint32_t)(i * 128 + b_l * 32 + d4) * 4;
                sts128f(sb + SM_XS + off, xv);
                sts128f(sb + SM_YS + off, yv);
            }
        }
        __syncthreads();

        // per-thread y registers: yA[row][q], j = 2*t3+(q&1)+((q>>1)&1)*8+(q>>2)*16
        float yA[2][8];
#pragma unroll
        for (int q = 0; q < 8; q++) {
            const int j = 2 * t3 + (q & 1) + ((q >> 1) & 1) * 8 + (q >> 2) * 16;
            yA[0][q] = ldsf(sb + SM_YS + (uint32_t)(j * 128 + r1) * 4);
            yA[1][q] = ldsf(sb + SM_YS + (uint32_t)(j * 128 + r2) * 4);
        }

        float acc[32];
#pragma unroll
        for (int z = 0; z < 32; z++) acc[z] = 0.0f;

        // ---------------- mainloop: i = 0..31, two k16-steps per i ----------
        for (int i = 0; i < 32; i++) {
            const float xf0 = ldsf(sb + SM_XS + (uint32_t)(i * 128 + r1) * 4);
            const float xf1 = ldsf(sb + SM_XS + (uint32_t)(i * 128 + r2) * 4);
#pragma unroll
            for (int h = 0; h < 2; h++) {
                const int s  = i * 2 + h;
                const int yb = h * 4;
                const uint32_t a0 = cvt2(xf0 * yA[0][yb + 1], xf0 * yA[0][yb + 0]);
                const uint32_t a1 = cvt2(xf1 * yA[1][yb + 1], xf1 * yA[1][yb + 0]);
                const uint32_t a2 = cvt2(xf0 * yA[0][yb + 3], xf0 * yA[0][yb + 2]);
                const uint32_t a3 = cvt2(xf1 * yA[1][yb + 3], xf1 * yA[1][yb + 2]);
                uint32_t bb[16];
                const uint32_t bbase = sb + SM_KP + (uint32_t)s * 2048 + lane * 16;
                lds128(bb + 0,  bbase + 0 * 512);
                lds128(bb + 4,  bbase + 1 * 512);
                lds128(bb + 8,  bbase + 2 * 512);
                lds128(bb + 12, bbase + 3 * 512);
#pragma unroll
                for (int tt = 0; tt < 8; tt++) {
                    const int bi = (tt >> 1) * 4 + (tt & 1) * 2;
                    mma16816(acc + tt * 4, a0, a1, a2, a3, bb[bi], bb[bi + 1]);
                }
            }
        }

        // ---------------- epilogue: frags -> padded SMEM -> coalesced gmem --
#pragma unroll
        for (int tt = 0; tt < 8; tt++) {
            const int c_lo = tt * 8 + 2 * t3;
            const uint32_t a1w = sb + SM_BUF + (uint32_t)(r1 * BUF_STRIDE + c_lo) * 4;
            const uint32_t a2w = sb + SM_BUF + (uint32_t)(r2 * BUF_STRIDE + c_lo) * 4;
            sts32f(a1w,     acc[tt * 4 + 0]);
            sts32f(a1w + 4, acc[tt * 4 + 1]);
            sts32f(a2w,     acc[tt * 4 + 2]);
            sts32f(a2w + 4, acc[tt * 4 + 3]);
        }
        __syncthreads();

        // each 8-lane group handles one (b_l, c) row of 32 d's per round
#pragma unroll
        for (int j = 0; j < 8; j++) {
            const int idx = (w * 8 + j) * 4 + (lane >> 3);  // 0..255
            const int b_l = idx >> 6;
            const int c   = idx & 63;
            const int db  = 4 * (lane & 7);
            float v0 = ldsf(sb + SM_BUF + (uint32_t)((b_l * 32 + db + 0) * BUF_STRIDE + c) * 4);
            float v1 = ldsf(sb + SM_BUF + (uint32_t)((b_l * 32 + db + 1) * BUF_STRIDE + c) * 4);
            float v2 = ldsf(sb + SM_BUF + (uint32_t)((b_l * 32 + db + 2) * BUF_STRIDE + c) * 4);
            float v3 = ldsf(sb + SM_BUF + (uint32_t)((b_l * 32 + db + 3) * BUF_STRIDE + c) * 4);
            float4 sv = make_float4(v0, v1, v2, v3);
            const int b = p * 4 + b_l;
            float* dst = out_mat + ((size_t)b * C_DIM + c) * D_DIM + db;
            *reinterpret_cast<float4*>(dst) = sv;
            float srow = (v0 + v1) + (v2 + v3);
            srow += __shfl_xor_sync(0xffffffffu, srow, 1);
            srow += __shfl_xor_sync(0xffffffffu, srow, 2);
            srow += __shfl_xor_sync(0xffffffffu, srow, 4);
            if ((lane & 7) == 0) out_fin[b * C_DIM + c] = srow;
        }
        // next pass's x/y staging is fenced by the __syncthreads at its start
        // (buf reads here complete before any thread passes that barrier and
        //  reaches the next buf writes, which sit after the next mainloop)
    }
}

}  // namespace cin

extern "C" void kernel_launch(void* const* d_in, const int* in_sizes, int n_in,
                              void* d_out, int out_size) {
    // Expected order: x [B,H1,D], y [B,H2,D], kernel [C,H1,H2].
    // Defensive remap: kernel is uniquely the 65536-element input.
    const float* x = (const float*)d_in[0];
    const float* y = (const float*)d_in[1];
    const float* k = (const float*)d_in[2];
    if (n_in == 3) {
        if (in_sizes[0] == C_DIM * H_DIM * H_DIM) {
            k = (const float*)d_in[0]; x = (const float*)d_in[1]; y = (const float*)d_in[2];
        } else if (in_sizes[1] == C_DIM * H_DIM * H_DIM) {
            x = (const float*)d_in[0]; k = (const float*)d_in[1]; y = (const float*)d_in[2];
        }
    }
    float* out_mat = (float*)d_out;
    float* out_fin = out_mat + (size_t)B_DIM * C_DIM * D_DIM;

    cudaFuncSetAttribute(cin::cin_kernel,
                         cudaFuncAttributeMaxDynamicSharedMemorySize,
                         cin::SMEM_TOTAL);
    cin::cin_kernel<<<cin::GRID, cin::THREADS, cin::SMEM_TOTAL>>>(
        x, y, k, out_mat, out_fin);
}